// round 17
// baseline (speedup 1.0000x reference)
#include <cuda_runtime.h>
#include <math.h>

#define D_MODEL 1024
#define SEQ     4096
#define NHEAD   16
#define DK      64

// Scratch (allocation-free: __device__ globals)
__device__ float g_Q[SEQ * D_MODEL];
__device__ float g_K[SEQ * D_MODEL];
__device__ float g_V[SEQ * D_MODEL];
__device__ float g_O[SEQ * D_MODEL];

// ---------------------------------------------------------------------------
// tf32 helpers. cvt.rna (round-to-nearest) is REQUIRED: raw-bit truncation in
// the mma gives a correlated -2^-11 bias per operand -> ~1e-3 systematic error.
// ---------------------------------------------------------------------------
__device__ __forceinline__ unsigned f2tf(float x) {
    unsigned y;
    asm("cvt.rna.tf32.f32 %0, %1;" : "=r"(y) : "f"(x));
    return y;
}

// D += A(16x8) * B(8x8), tf32 in, fp32 accum
__device__ __forceinline__ void mma8(float* d, const unsigned* a, const unsigned* b) {
    asm volatile(
        "mma.sync.aligned.m16n8k8.row.col.f32.tf32.tf32.f32 "
        "{%0,%1,%2,%3}, {%4,%5,%6,%7}, {%8,%9}, {%0,%1,%2,%3};\n"
        : "+f"(d[0]), "+f"(d[1]), "+f"(d[2]), "+f"(d[3])
        : "r"(a[0]), "r"(a[1]), "r"(a[2]), "r"(a[3]), "r"(b[0]), "r"(b[1]));
}

// Permutation within each 8-wide k-block so that the (c, c+4) fragment pair is
// adjacent in smem -> every fragment load is one LDS.64. (attention kernel)
__device__ __forceinline__ int kperm(int k) {
    return (k & ~7) + ((k & 3) << 1) + ((k >> 2) & 1);
}

// 16-byte async copy global -> shared (raw bits, no conversion)
__device__ __forceinline__ void cp16(const float* smem_dst, const float* gsrc) {
    unsigned saddr = (unsigned)__cvta_generic_to_shared(smem_dst);
    asm volatile("cp.async.ca.shared.global [%0], [%1], 16;"
                 :: "r"(saddr), "l"(gsrc));
}

// ============================================================================
// GEMM: C[M,1024] = A[M,1024] @ W[1024,1024]^T + bias  (tf32 mma, NT)
// Tile 128x128xBK32, 8 warps as 2(M)x4(N), warp tile 64x32.
// 3-STAGE cp.async pipeline, ONE barrier + ONE wait_group<1> per slab:
//   wait_group 1  -> slab kc landed (slab kc+1's group may still fly)
//   __syncthreads -> slab kc visible; compute(kc-1) done -> stage (kc+2)%3 free
//   issue copy(kc+2), commit (empty commit in tail keeps accounting uniform)
//   compute(kc)
// Row stride 36 words: fragment banks (36g+c)%32 = 4g+c cover 0..31 exactly
// -> every scalar LDS is conflict-free; 36*16 % 32 == 0 keeps rows neutral.
// cvt.rna at fragment load (numerics identical to previous rounds).
// ============================================================================
#define GSTR3 36
#define GCH3  (128 * GSTR3)      // words per matrix per stage (4608)
#define GSTG3 (2 * GCH3)         // words per stage: A then B (9216)
#define NSLAB (D_MODEL / 32)     // 32
#define GSMEM (3 * GSTG3 * (int)sizeof(float))   // 110592 B -> 2 CTAs/SM

__device__ __forceinline__ void gemm_core(const float* __restrict__ A,
                                          const float* __restrict__ W,
                                          const float* __restrict__ bias,
                                          float* __restrict__ C,
                                          int bx, int by) {
    extern __shared__ float gsm[];   // [3][A:128x36 | B:128x36] raw f32

    const int tid  = threadIdx.x;
    const int lane = tid & 31;
    const int warp = tid >> 5;
    const int g = lane >> 2, c = lane & 3;
    const int wm = (warp >> 2) * 64;      // 0 / 64
    const int wn = (warp & 3) * 32;       // 0,32,64,96
    const int bm = by * 128;
    const int bn = bx * 128;

    // cp.async mapping: 4 chunks per thread per matrix per stage (128x32 f32)
    int rowp[4], jp[4];
#pragma unroll
    for (int p = 0; p < 4; p++) {
        const int lin = tid + p * 256;
        rowp[p] = lin >> 3;           // 0..127
        jp[p]   = (lin & 7) * 4;      // 0,4,...,28
    }

    float acc[4][4][4];
#pragma unroll
    for (int i = 0; i < 4; i++)
#pragma unroll
        for (int j = 0; j < 4; j++)
#pragma unroll
            for (int r = 0; r < 4; r++) acc[i][j][r] = 0.0f;

    // prologue: issue slabs 0 and 1 into stages 0 and 1
#pragma unroll
    for (int s = 0; s < 2; s++) {
        float* st = gsm + s * GSTG3;
        const int k0 = s * 32;
#pragma unroll
        for (int p = 0; p < 4; p++) {
            cp16(st + rowp[p] * GSTR3 + jp[p],
                 A + (size_t)(bm + rowp[p]) * D_MODEL + k0 + jp[p]);
            cp16(st + GCH3 + rowp[p] * GSTR3 + jp[p],
                 W + (size_t)(bn + rowp[p]) * D_MODEL + k0 + jp[p]);
        }
        asm volatile("cp.async.commit_group;" ::: "memory");
    }

    int cur = 0, wr = 2;   // stage indices mod 3
    for (int kc = 0; kc < NSLAB; kc++) {
        asm volatile("cp.async.wait_group 1;" ::: "memory");
        __syncthreads();   // slab kc visible to all; compute(kc-1) done by all

        // issue slab kc+2 into stage wr (flies during compute of kc and kc+1)
        if (kc + 2 < NSLAB) {
            float* st = gsm + wr * GSTG3;
            const int k0 = (kc + 2) * 32;
#pragma unroll
            for (int p = 0; p < 4; p++) {
                cp16(st + rowp[p] * GSTR3 + jp[p],
                     A + (size_t)(bm + rowp[p]) * D_MODEL + k0 + jp[p]);
                cp16(st + GCH3 + rowp[p] * GSTR3 + jp[p],
                     W + (size_t)(bn + rowp[p]) * D_MODEL + k0 + jp[p]);
            }
        }
        asm volatile("cp.async.commit_group;" ::: "memory");   // empty in tail

        const float* Acur = gsm + cur * GSTG3;
        const float* Bcur = Acur + GCH3;

#pragma unroll
        for (int s = 0; s < 4; s++) {
            unsigned af[4][4], bf[4][2];
#pragma unroll
            for (int ma = 0; ma < 4; ma++) {
                const int base = (wm + ma * 16 + g) * GSTR3 + s * 8 + c;
                af[ma][0] = f2tf(Acur[base]);
                af[ma][1] = f2tf(Acur[base + 8 * GSTR3]);
                af[ma][2] = f2tf(Acur[base + 4]);
                af[ma][3] = f2tf(Acur[base + 8 * GSTR3 + 4]);
            }
#pragma unroll
            for (int na = 0; na < 4; na++) {
                const int base = (wn + na * 8 + g) * GSTR3 + s * 8 + c;
                bf[na][0] = f2tf(Bcur[base]);
                bf[na][1] = f2tf(Bcur[base + 4]);
            }
#pragma unroll
            for (int ma = 0; ma < 4; ma++)
#pragma unroll
                for (int na = 0; na < 4; na++)
                    mma8(acc[ma][na], af[ma], bf[na]);
        }
        cur = (cur == 2) ? 0 : cur + 1;
        wr  = (wr  == 2) ? 0 : wr  + 1;
    }

    // epilogue: + bias, float2 stores
#pragma unroll
    for (int na = 0; na < 4; na++) {
        const int col = bn + wn + na * 8 + 2 * c;
        const float2 bb = *(const float2*)(bias + col);
#pragma unroll
        for (int ma = 0; ma < 4; ma++) {
            const int r0 = bm + wm + ma * 16 + g;
            float2 v0 = {acc[ma][na][0] + bb.x, acc[ma][na][1] + bb.y};
            float2 v1 = {acc[ma][na][2] + bb.x, acc[ma][na][3] + bb.y};
            *(float2*)(C + (size_t)r0 * D_MODEL + col)       = v0;
            *(float2*)(C + (size_t)(r0 + 8) * D_MODEL + col) = v1;
        }
    }
}

// Fused Q/K/V projection: blockIdx.z selects {query,key,value} x {Wq,Wk,Wv}.
__global__ __launch_bounds__(256, 2)
void gemm_qkv(const float* __restrict__ xq, const float* __restrict__ xk,
              const float* __restrict__ xv,
              const float* __restrict__ Wq, const float* __restrict__ bq,
              const float* __restrict__ Wk, const float* __restrict__ bk,
              const float* __restrict__ Wv, const float* __restrict__ bv,
              float* __restrict__ Cq, float* __restrict__ Ck, float* __restrict__ Cv) {
    const float *A, *W, *b;
    float* C;
    if (blockIdx.z == 0)      { A = xq; W = Wq; b = bq; C = Cq; }
    else if (blockIdx.z == 1) { A = xk; W = Wk; b = bk; C = Ck; }
    else                      { A = xv; W = Wv; b = bv; C = Cv; }
    gemm_core(A, W, b, C, blockIdx.x, blockIdx.y);
}

__global__ __launch_bounds__(256, 2)
void gemm_one(const float* __restrict__ A, const float* __restrict__ W,
              const float* __restrict__ bias, float* __restrict__ C) {
    gemm_core(A, W, bias, C, blockIdx.x, blockIdx.y);
}

// ============================================================================
// Flash attention, tf32 mma. One CTA = (head, 128-query block), 2 CTAs/SM.
// 8 warps x 16 query rows; 64-key blocks. Same math/layout as the 955us
// version, plus ONE change: K/V for block kb+1 are prefetched into registers
// AFTER the softmax (lifetime spans only PV, so the softmax register peak is
// untouched) and stored to smem at the next block top — the previously
// exposed LDG->STS stall right after the barrier disappears.
// ============================================================================
#define ASTR 72
#define MQ   128

__global__ __launch_bounds__(256, 2)
void attn_tf32(const float* __restrict__ Qb, const float* __restrict__ Kb,
               const float* __restrict__ Vb, float* __restrict__ Ob) {
    extern __shared__ unsigned smA[];
    unsigned* Qs = smA;                 // [MQ][ASTR]  perm(d)
    unsigned* Ps = Qs + MQ * ASTR;      // [MQ][ASTR]  perm(key)
    unsigned* Ks = Ps + MQ * ASTR;      // [64][ASTR]  perm(d)
    unsigned* Vs = Ks + 64 * ASTR;      // [64][ASTR]  plain d

    const int tid = threadIdx.x, lane = tid & 31, warp = tid >> 5;
    const int g = lane >> 2, c = lane & 3;
    const int h = blockIdx.y, q0 = blockIdx.x * MQ, c0 = h * DK;
    const int wq = warp * 16;

    const float QS = 0.125f * 1.4426950408889634f;   // (1/sqrt(dk)) * log2(e)

    // staging coordinates (same for K and V, 4 passes)
    int rr[4], dd[4];
#pragma unroll
    for (int p = 0; p < 4; p++) {
        const int idx = p * 1024 + tid * 4;
        rr[p] = idx >> 6;
        dd[p] = idx & 63;
    }

    // ---- stage Q (scaled, tf32, perm) : 8 passes ----
#pragma unroll
    for (int p = 0; p < (MQ * DK) / (256 * 4); p++) {
        const int idx = p * 1024 + tid * 4;
        const int r = idx >> 6, d0 = idx & 63;
        const float4 v = *(const float4*)(Qb + (q0 + r) * D_MODEL + c0 + d0);
        unsigned* dst = Qs + r * ASTR;
        const float vv[4] = {v.x, v.y, v.z, v.w};
#pragma unroll
        for (int j = 0; j < 4; j++) dst[kperm(d0 + j)] = f2tf(vv[j] * QS);
    }

    // ---- prefetch K/V block 0 into registers ----
    float4 kreg[4], vreg[4];
#pragma unroll
    for (int p = 0; p < 4; p++) {
        kreg[p] = *(const float4*)(Kb + rr[p] * D_MODEL + c0 + dd[p]);
        vreg[p] = *(const float4*)(Vb + rr[p] * D_MODEL + c0 + dd[p]);
    }

    float o[8][4];
    float mrun[2], lrun[2];
    mrun[0] = mrun[1] = -1e30f;
    lrun[0] = lrun[1] = 0.0f;
#pragma unroll
    for (int na = 0; na < 8; na++)
#pragma unroll
        for (int r = 0; r < 4; r++) o[na][r] = 0.0f;

    const int pe = ((2 * c) & 3) * 2 + (((2 * c) >> 2) & 1);          // {0,4,1,5}
    const int po = ((2 * c + 1) & 3) * 2 + (((2 * c + 1) >> 2) & 1);  // {2,6,3,7}

    for (int kb = 0; kb < SEQ / 64; kb++) {
        __syncthreads();   // previous PV readers of Ks/Vs done (covers Qs on kb=0)

        // ---- STS K (perm) and V (plain) from prefetch registers ----
#pragma unroll
        for (int p = 0; p < 4; p++) {
            unsigned* kd = Ks + rr[p] * ASTR;
            kd[kperm(dd[p] + 0)] = f2tf(kreg[p].x);
            kd[kperm(dd[p] + 1)] = f2tf(kreg[p].y);
            kd[kperm(dd[p] + 2)] = f2tf(kreg[p].z);
            kd[kperm(dd[p] + 3)] = f2tf(kreg[p].w);
            uint4 vt;
            vt.x = f2tf(vreg[p].x); vt.y = f2tf(vreg[p].y);
            vt.z = f2tf(vreg[p].z); vt.w = f2tf(vreg[p].w);
            *(uint4*)(Vs + rr[p] * ASTR + dd[p]) = vt;
        }
        __syncthreads();

        // ---- S = Q K^T (per warp: 16 q-rows x 64 keys) ----
        float sa[8][4];
#pragma unroll
        for (int na = 0; na < 8; na++)
#pragma unroll
            for (int r = 0; r < 4; r++) sa[na][r] = 0.0f;

#pragma unroll
        for (int s = 0; s < 8; s++) {
            unsigned aq[4];
            {
                const uint2 t0 = *(const uint2*)(Qs + (wq + g)     * ASTR + s * 8 + 2 * c);
                const uint2 t1 = *(const uint2*)(Qs + (wq + g + 8) * ASTR + s * 8 + 2 * c);
                aq[0] = t0.x; aq[1] = t1.x; aq[2] = t0.y; aq[3] = t1.y;
            }
#pragma unroll
            for (int na = 0; na < 8; na++) {
                const uint2 t = *(const uint2*)(Ks + (na * 8 + g) * ASTR + s * 8 + 2 * c);
                unsigned bk[2] = {t.x, t.y};
                mma8(sa[na], aq, bk);
            }
        }

        // ---- online softmax (exp2 domain) + stage P (tf32, perm) ----
#pragma unroll
        for (int hf = 0; hf < 2; hf++) {
            float mx = -1e30f;
#pragma unroll
            for (int na = 0; na < 8; na++)
                mx = fmaxf(mx, fmaxf(sa[na][2 * hf], sa[na][2 * hf + 1]));
            mx = fmaxf(mx, __shfl_xor_sync(0xffffffffu, mx, 1));
            mx = fmaxf(mx, __shfl_xor_sync(0xffffffffu, mx, 2));
            const float mnew  = fmaxf(mrun[hf], mx);
            const float alpha = exp2f(mrun[hf] - mnew);
            mrun[hf] = mnew;

            float rs = 0.0f;
            unsigned* prow = Ps + (wq + hf * 8 + g) * ASTR;
#pragma unroll
            for (int na = 0; na < 8; na++) {
                const float p0 = exp2f(sa[na][2 * hf]     - mnew);
                const float p1 = exp2f(sa[na][2 * hf + 1] - mnew);
                rs += p0 + p1;
                prow[na * 8 + pe] = f2tf(p0);
                prow[na * 8 + po] = f2tf(p1);
                o[na][2 * hf]     *= alpha;
                o[na][2 * hf + 1] *= alpha;
            }
            rs += __shfl_xor_sync(0xffffffffu, rs, 1);
            rs += __shfl_xor_sync(0xffffffffu, rs, 2);
            lrun[hf] = lrun[hf] * alpha + rs;
        }
        __syncwarp();   // P rows are warp-local: cross-lane visibility only

        // ---- prefetch K/V block kb+1 (latency hidden under PV below;
        //      register lifetime spans only PV, not the softmax peak) ----
        if (kb + 1 < SEQ / 64) {
            const int kr2 = (kb + 1) * 64;
#pragma unroll
            for (int p = 0; p < 4; p++) {
                kreg[p] = *(const float4*)(Kb + (kr2 + rr[p]) * D_MODEL + c0 + dd[p]);
                vreg[p] = *(const float4*)(Vb + (kr2 + rr[p]) * D_MODEL + c0 + dd[p]);
            }
        }

        // ---- O += P V (contraction over 64 keys) ----
#pragma unroll
        for (int s = 0; s < 8; s++) {
            unsigned ap[4];
            {
                const uint2 t0 = *(const uint2*)(Ps + (wq + g)     * ASTR + s * 8 + 2 * c);
                const uint2 t1 = *(const uint2*)(Ps + (wq + g + 8) * ASTR + s * 8 + 2 * c);
                ap[0] = t0.x; ap[1] = t1.x; ap[2] = t0.y; ap[3] = t1.y;
            }
#pragma unroll
            for (int na = 0; na < 8; na++) {
                unsigned bv[2];
                bv[0] = Vs[(s * 8 + c)     * ASTR + na * 8 + g];
                bv[1] = Vs[(s * 8 + c + 4) * ASTR + na * 8 + g];
                mma8(o[na], ap, bv);
            }
        }
    }

    // ---- epilogue: O /= l, write concat-head layout [S, D_MODEL] ----
#pragma unroll
    for (int hf = 0; hf < 2; hf++) {
        const float inv = 1.0f / lrun[hf];
        const int row = q0 + wq + hf * 8 + g;
#pragma unroll
        for (int na = 0; na < 8; na++) {
            float2 w;
            w.x = o[na][2 * hf]     * inv;
            w.y = o[na][2 * hf + 1] * inv;
            *(float2*)(Ob + row * D_MODEL + c0 + na * 8 + 2 * c) = w;
        }
    }
}

// ============================================================================
// Launch
// ============================================================================
extern "C" void kernel_launch(void* const* d_in, const int* in_sizes, int n_in,
                              void* d_out, int out_size) {
    (void)in_sizes; (void)n_in; (void)out_size;
    const float* query = (const float*)d_in[0];
    const float* key   = (const float*)d_in[1];
    const float* value = (const float*)d_in[2];
    const float* Wq = (const float*)d_in[3];
    const float* bq = (const float*)d_in[4];
    const float* Wk = (const float*)d_in[5];
    const float* bk = (const float*)d_in[6];
    const float* Wv = (const float*)d_in[7];
    const float* bv = (const float*)d_in[8];
    const float* Wo = (const float*)d_in[9];
    const float* bo = (const float*)d_in[10];
    float* out = (float*)d_out;

    float *pQ, *pK, *pV, *pO;
    cudaGetSymbolAddress((void**)&pQ, g_Q);
    cudaGetSymbolAddress((void**)&pK, g_K);
    cudaGetSymbolAddress((void**)&pV, g_V);
    cudaGetSymbolAddress((void**)&pO, g_O);

    const int ASMEM = (2 * MQ + 2 * 64) * ASTR * (int)sizeof(unsigned);  // 110592 B
    cudaFuncSetAttribute(gemm_qkv, cudaFuncAttributeMaxDynamicSharedMemorySize, GSMEM);
    cudaFuncSetAttribute(gemm_one, cudaFuncAttributeMaxDynamicSharedMemorySize, GSMEM);
    cudaFuncSetAttribute(attn_tf32, cudaFuncAttributeMaxDynamicSharedMemorySize, ASMEM);

    dim3 gq(D_MODEL / 128, SEQ / 128, 3);   // (8, 32, 3)
    gemm_qkv<<<gq, 256, GSMEM>>>(query, key, value, Wq, bq, Wk, bk, Wv, bv,
                                 pQ, pK, pV);

    dim3 ga(SEQ / MQ, NHEAD);               // (32, 16)
    attn_tf32<<<ga, 256, ASMEM>>>(pQ, pK, pV, pO);

    dim3 gg(D_MODEL / 128, SEQ / 128);      // (8, 32)
    gemm_one<<<gg, 256, GSMEM>>>(pO, Wo, bo, out);
}